// round 12
// baseline (speedup 1.0000x reference)
#include <cuda_runtime.h>
#include <cstdint>

typedef uint32_t u32;

// Problem constants
#define BB 2
#define SS 1024
#define HH 8
#define DD 64
#define RR 32
#define KW 128
#define CC (HH*DD)          // 512
#define ZLEN (4*KW+SS)      // 1536
#define TS 64               // s per CTA
#define NTHREADS 128
#define DSPLIT 4            // d-reduction split across CTAs
#define DLOC (DD/DSPLIT)    // 16 d per CTA

#define OUTN (BB*SS*HH*RR*2)   // 1,048,576 floats (qhat+khat)

// partial sums for dh = 1..3
__device__ float g_part[3][OUTN];

// SMEM layout (no QK buffer anymore -> 54.3 KB -> 4 CTAs/SM)
#define ZSTRIDE 196                         // words/row (conflict-free, 16B-aligned)
#define Z_BYTES   (RR * ZSTRIDE * 4)        // 25088 per buffer
#define W_BYTES   (2 * 256 * 4)             // 2048 per buffer (zero-padded filters)
#define DYN_BYTES (2*Z_BYTES + 2*W_BYTES)   // 54272

__device__ __forceinline__ u32 smem_u32(const void* p) {
    u32 a; asm("{ .reg .u64 t; cvta.to.shared.u64 t, %1; cvt.u32.u64 %0, t; }"
               : "=r"(a) : "l"(p));
    return a;
}
__device__ __forceinline__ void cpasync16(u32 dst, const void* src) {
    asm volatile("cp.async.cg.shared.global [%0], [%1], 16;" :: "r"(dst), "l"(src));
}
__device__ __forceinline__ void cpasync4(u32 dst, const void* src) {
    asm volatile("cp.async.ca.shared.global [%0], [%1], 4;" :: "r"(dst), "l"(src));
}
__device__ __forceinline__ void cp_commit() {
    asm volatile("cp.async.commit_group;" ::: "memory");
}
__device__ __forceinline__ void cp_wait_all() {
    asm volatile("cp.async.wait_group 0;" ::: "memory");
}

__device__ __forceinline__ u32 cvt_tf32(float x) {
    u32 r; asm("cvt.rna.tf32.f32 %0, %1;" : "=r"(r) : "f"(x)); return r;
}

__device__ __forceinline__ void mma_acc(float* c,
                                        u32 a0, u32 a1, u32 a2, u32 a3,
                                        u32 b0, u32 b1) {
    asm volatile(
        "mma.sync.aligned.m16n8k8.row.col.f32.tf32.tf32.f32 "
        "{%0,%1,%2,%3}, {%4,%5,%6,%7}, {%8,%9}, {%0,%1,%2,%3};"
        : "+f"(c[0]), "+f"(c[1]), "+f"(c[2]), "+f"(c[3])
        : "r"(a0), "r"(a1), "r"(a2), "r"(a3), "r"(b0), "r"(b1));
}
__device__ __forceinline__ void mma_init(float* c,
                                         u32 a0, u32 a1, u32 a2, u32 a3,
                                         u32 b0, u32 b1) {
    asm volatile(
        "mma.sync.aligned.m16n8k8.row.col.f32.tf32.tf32.f32 "
        "{%0,%1,%2,%3}, {%4,%5,%6,%7}, {%8,%9}, {%10,%11,%12,%13};"
        : "=f"(c[0]), "=f"(c[1]), "=f"(c[2]), "=f"(c[3])
        : "r"(a0), "r"(a1), "r"(a2), "r"(a3), "r"(b0), "r"(b1),
          "f"(0.f), "f"(0.f), "f"(0.f), "f"(0.f));
}

struct PrefetchCtx {
    const float* zg;
    const float* wq;
    const float* wk;
    u32 zsu0, zsu1, wsu0, wsu1;
    int tid, b, s0, cbase;
};

__device__ __forceinline__ void prefetch_d(const PrefetchCtx& P, int dd) {
    const int c   = P.cbase + dd;
    const u32 zsu = (dd & 1) ? P.zsu1 : P.zsu0;
    const u32 wsu = (dd & 1) ? P.wsu1 : P.wsu0;
    #pragma unroll
    for (int i = 0; i < 12; i++) {
        int idx  = P.tid + i * NTHREADS;
        int zrow = idx / 48;
        int gq   = idx - zrow * 48;
        const float* src = P.zg + ((size_t)((P.b * RR + zrow) * CC + c)) * ZLEN
                         + KW + P.s0 + gq * 4;
        cpasync16(zsu + (u32)(zrow * ZSTRIDE + gq * 4) * 4u, src);
    }
    cpasync4(wsu + (64 + P.tid) * 4,       P.wk + c * KW + P.tid);
    cpasync4(wsu + (256 + 64 + P.tid) * 4, P.wq + c * KW + P.tid);
    cp_commit();
}

__global__ __launch_bounds__(NTHREADS, 4)
void convspe_mma_kernel(const float* __restrict__ qg,
                        const float* __restrict__ kg,
                        const float* __restrict__ wq,
                        const float* __restrict__ wk,
                        const float* __restrict__ zg,
                        float* __restrict__ out)
{
    extern __shared__ char dyn[];
    u32*   Zs0 = reinterpret_cast<u32*>(dyn);
    u32*   Zs1 = reinterpret_cast<u32*>(dyn + Z_BYTES);
    float* W0  = reinterpret_cast<float*>(dyn + 2 * Z_BYTES);
    float* W1  = reinterpret_cast<float*>(dyn + 2 * Z_BYTES + W_BYTES);

    const int tid  = threadIdx.x;
    const int w    = tid >> 5;
    const int lane = tid & 31;
    const int g    = lane >> 2;       // row group 0..7
    const int qi   = lane & 3;        // quad index 0..3

    const int stile = blockIdx.x;     // 0..15
    const int h     = blockIdx.y;     // 0..7
    const int bz    = blockIdx.z;     // 0..7
    const int b     = bz >> 2;
    const int dh    = bz & 3;         // d-split index
    const int dbase = dh * DLOC;
    const int s0    = stile * TS;
    const int cbase = h * DD + dbase;

    // ---- zero-fill both W pads once (out-of-band entries stay 0 forever) ----
    #pragma unroll
    for (int i = 0; i < 4; i++) {
        W0[tid + i * NTHREADS] = 0.f;
        W1[tid + i * NTHREADS] = 0.f;
    }

    PrefetchCtx P { zg, wq, wk,
                    smem_u32(Zs0), smem_u32(Zs1), smem_u32(W0), smem_u32(W1),
                    tid, b, s0, cbase };

    // ---- prefetch d = 0 ----
    prefetch_d(P, 0);

    // ---- per-warp constants: warp owns 2 m-tiles of one filter half ----
    const int f      = w >> 1;          // 0: qhat rows (filter wk), 1: khat rows (filter wq)
    const int c0     = (w & 1) * 4;     // chunk base
    const int qg_off = qi - g;          // lane band offset

    // ---- q/k scalars via registers with 1-deep pipeline (no QK smem) ----
    // thread covers rows srow0 + {0,8,16,24} of its filter half's s-block
    const int srow0 = (w & 1) * 32 + g;
    const float* qk  = (f == 0) ? qg : kg;
    const float* pv0 = qk + ((size_t)((b * SS + s0 + srow0) * HH + h)) * DD + dbase;
    const size_t vstp = (size_t)8 * HH * DD;    // 8 s-rows

    float qvc[4], qvn[4];
    #pragma unroll
    for (int j = 0; j < 4; j++) qvc[j] = pv0[j * vstp];   // d = 0

    float acc0[4][4], acc1[4][4];       // running d-sums for m-tile0 / m-tile1
    #pragma unroll
    for (int n = 0; n < 4; n++)
        #pragma unroll
        for (int i = 0; i < 4; i++) { acc0[n][i] = 0.f; acc1[n][i] = 0.f; }

    for (int d = 0; d < DLOC; d++) {
        cp_wait_all();        // this thread's cp.async group for d complete
        __syncthreads();      // data for d visible; iteration d-1 consumers done

        if (d + 1 < DLOC) {
            prefetch_d(P, d + 1);   // overlaps the MMA loop below
            #pragma unroll
            for (int j = 0; j < 4; j++) qvn[j] = pv0[j * vstp + d + 1];
        }

        const u32*   Zs = (d & 1) ? Zs1 : Zs0;
        const float* wp = ((d & 1) ? W1 : W0) + f * 256;

        // -- sliding A-frag window: w0[i] = aw0[u+i], w2[i] = aw2[u+i] --
        u32 w0[4], w2[4];
        #pragma unroll
        for (int i = 0; i < 4; i++) {
            w0[i] = cvt_tf32(wp[40 + 8 * i + qg_off]);
            w2[i] = cvt_tf32(wp[44 + 8 * i + qg_off]);
        }

        // -- per-d conv via MMA: work = W_band x Z (no q scaling) --
        float work0[4][4], work1[4][4];

        #pragma unroll
        for (int u = 0; u < 20; u++) {
            const int kg = (c0 + u) * 8 + qi;
            u32 b0[4], b1[4];
            #pragma unroll
            for (int n = 0; n < 4; n++) {
                const u32* zr = Zs + (n * 8 + g) * ZSTRIDE + kg;
                b0[n] = zr[0];
                b1[n] = zr[4];
            }

            if (u < 18) {   // m-tile 0: frags aw[u+3], aw[u+2]
                if (u == 0) {
                    #pragma unroll
                    for (int n = 0; n < 4; n++)
                        mma_init(work0[n], w0[3], w0[2], w2[3], w2[2], b0[n], b1[n]);
                } else {
                    #pragma unroll
                    for (int n = 0; n < 4; n++)
                        mma_acc(work0[n], w0[3], w0[2], w2[3], w2[2], b0[n], b1[n]);
                }
            }
            if (u >= 2) {   // m-tile 1: frags aw[u+1], aw[u]
                if (u == 2) {
                    #pragma unroll
                    for (int n = 0; n < 4; n++)
                        mma_init(work1[n], w0[1], w0[0], w2[1], w2[0], b0[n], b1[n]);
                } else {
                    #pragma unroll
                    for (int n = 0; n < 4; n++)
                        mma_acc(work1[n], w0[1], w0[0], w2[1], w2[0], b0[n], b1[n]);
                }
            }

            // -- slide window (register renames under full unroll) --
            if (u < 19) {
                w0[0] = w0[1]; w0[1] = w0[2]; w0[2] = w0[3];
                w2[0] = w2[1]; w2[1] = w2[2]; w2[2] = w2[3];
                w0[3] = cvt_tf32(wp[40 + 8 * (u + 4) + qg_off]);
                w2[3] = cvt_tf32(wp[44 + 8 * (u + 4) + qg_off]);
            }
        }

        // -- scale by q/k at (s, d) and accumulate over d (exact fp32) --
        #pragma unroll
        for (int n = 0; n < 4; n++) {
            acc0[n][0] = fmaf(qvc[0], work0[n][0], acc0[n][0]);
            acc0[n][1] = fmaf(qvc[0], work0[n][1], acc0[n][1]);
            acc0[n][2] = fmaf(qvc[1], work0[n][2], acc0[n][2]);
            acc0[n][3] = fmaf(qvc[1], work0[n][3], acc0[n][3]);
            acc1[n][0] = fmaf(qvc[2], work1[n][0], acc1[n][0]);
            acc1[n][1] = fmaf(qvc[2], work1[n][1], acc1[n][1]);
            acc1[n][2] = fmaf(qvc[3], work1[n][2], acc1[n][2]);
            acc1[n][3] = fmaf(qvc[3], work1[n][3], acc1[n][3]);
        }
        #pragma unroll
        for (int j = 0; j < 4; j++) qvc[j] = qvn[j];
        // no trailing __syncthreads: the top-of-loop barrier at d+1 orders
        // this iteration's smem reads against the buffer refill at d+2
    }

    // ---- epilogue: dh==0 writes out directly, others write partial scratch ----
    float* obase0 = (dh == 0) ? out : g_part[dh - 1];
    const int khat_off = BB * SS * HH * RR;
    #pragma unroll
    for (int mt = 0; mt < 2; mt++) {
        const int srow = (w & 1) * 32 + mt * 16 + g;
        float* ob  = obase0 + (f ? khat_off : 0)
                   + ((b * SS + s0 + srow) * HH + h) * RR;
        float* ob8 = ob + 8 * HH * RR;     // srow + 8
        #pragma unroll
        for (int n = 0; n < 4; n++) {
            const int col = n * 8 + 2 * qi;
            const float (*acc)[4] = mt ? acc1 : acc0;
            *reinterpret_cast<float2*>(ob  + col) = make_float2(acc[n][0], acc[n][1]);
            *reinterpret_cast<float2*>(ob8 + col) = make_float2(acc[n][2], acc[n][3]);
        }
    }
}

// deterministic combine: out += part0 + part1 + part2
__global__ __launch_bounds__(256)
void convspe_combine_kernel(float* __restrict__ out)
{
    int i = blockIdx.x * blockDim.x + threadIdx.x;   // float4 index
    if (i >= OUTN / 4) return;
    float4 o  = reinterpret_cast<float4*>(out)[i];
    float4 p0 = reinterpret_cast<const float4*>(g_part[0])[i];
    float4 p1 = reinterpret_cast<const float4*>(g_part[1])[i];
    float4 p2 = reinterpret_cast<const float4*>(g_part[2])[i];
    o.x += p0.x + p1.x + p2.x;
    o.y += p0.y + p1.y + p2.y;
    o.z += p0.z + p1.z + p2.z;
    o.w += p0.w + p1.w + p2.w;
    reinterpret_cast<float4*>(out)[i] = o;
}

extern "C" void kernel_launch(void* const* d_in, const int* in_sizes, int n_in,
                              void* d_out, int out_size)
{
    const float* queries = (const float*)d_in[0];
    const float* keys    = (const float*)d_in[1];
    const float* wq      = (const float*)d_in[2];
    const float* wk      = (const float*)d_in[3];
    const float* z       = (const float*)d_in[4];
    float* out = (float*)d_out;

    cudaFuncSetAttribute(convspe_mma_kernel,
                         cudaFuncAttributeMaxDynamicSharedMemorySize, DYN_BYTES);

    dim3 grid(SS / TS, HH, BB * DSPLIT);   // 16 x 8 x 8 = 1024 CTAs
    dim3 block(NTHREADS);
    convspe_mma_kernel<<<grid, block, DYN_BYTES>>>(queries, keys, wq, wk, z, out);

    int n4 = OUTN / 4;
    convspe_combine_kernel<<<(n4 + 255) / 256, 256>>>(out);
}

// round 13
// speedup vs baseline: 1.0567x; 1.0567x over previous
#include <cuda_runtime.h>
#include <cstdint>

typedef uint32_t u32;

// Problem constants
#define BB 2
#define SS 1024
#define HH 8
#define DD 64
#define RR 32
#define KW 128
#define CC (HH*DD)          // 512
#define ZLEN (4*KW+SS)      // 1536
#define TS 64               // s per CTA
#define NTHREADS 128
#define DSPLIT 8            // d-reduction split across CTAs (wave smoothing)
#define DLOC (DD/DSPLIT)    // 8 d per CTA

#define OUTN (BB*SS*HH*RR*2)   // 1,048,576 floats (qhat+khat)

// partial sums for dh = 1..7
__device__ float g_part[DSPLIT-1][OUTN];

// SMEM layout
#define ZSTRIDE 196                         // words/row (conflict-free, 16B-aligned)
#define Z_BYTES   (RR * ZSTRIDE * 4)        // 25088 per buffer
#define QKSTRIDE 132
#define QK_BYTES  (DLOC * QKSTRIDE * 4)     // 4224
#define W_BYTES   (2 * 256 * 4)             // 2048 per buffer (zero-padded filters)
#define DYN_BYTES (2*Z_BYTES + QK_BYTES + 2*W_BYTES)   // 58496 -> 3 CTAs/SM

__device__ __forceinline__ u32 smem_u32(const void* p) {
    u32 a; asm("{ .reg .u64 t; cvta.to.shared.u64 t, %1; cvt.u32.u64 %0, t; }"
               : "=r"(a) : "l"(p));
    return a;
}
__device__ __forceinline__ void cpasync16(u32 dst, const void* src) {
    asm volatile("cp.async.cg.shared.global [%0], [%1], 16;" :: "r"(dst), "l"(src));
}
__device__ __forceinline__ void cpasync4(u32 dst, const void* src) {
    asm volatile("cp.async.ca.shared.global [%0], [%1], 4;" :: "r"(dst), "l"(src));
}
__device__ __forceinline__ void cp_commit() {
    asm volatile("cp.async.commit_group;" ::: "memory");
}
__device__ __forceinline__ void cp_wait_all() {
    asm volatile("cp.async.wait_group 0;" ::: "memory");
}

__device__ __forceinline__ u32 cvt_tf32(float x) {
    u32 r; asm("cvt.rna.tf32.f32 %0, %1;" : "=r"(r) : "f"(x)); return r;
}

__device__ __forceinline__ void mma_acc(float* c,
                                        u32 a0, u32 a1, u32 a2, u32 a3,
                                        u32 b0, u32 b1) {
    asm volatile(
        "mma.sync.aligned.m16n8k8.row.col.f32.tf32.tf32.f32 "
        "{%0,%1,%2,%3}, {%4,%5,%6,%7}, {%8,%9}, {%0,%1,%2,%3};"
        : "+f"(c[0]), "+f"(c[1]), "+f"(c[2]), "+f"(c[3])
        : "r"(a0), "r"(a1), "r"(a2), "r"(a3), "r"(b0), "r"(b1));
}
__device__ __forceinline__ void mma_init(float* c,
                                         u32 a0, u32 a1, u32 a2, u32 a3,
                                         u32 b0, u32 b1) {
    asm volatile(
        "mma.sync.aligned.m16n8k8.row.col.f32.tf32.tf32.f32 "
        "{%0,%1,%2,%3}, {%4,%5,%6,%7}, {%8,%9}, {%10,%11,%12,%13};"
        : "=f"(c[0]), "=f"(c[1]), "=f"(c[2]), "=f"(c[3])
        : "r"(a0), "r"(a1), "r"(a2), "r"(a3), "r"(b0), "r"(b1),
          "f"(0.f), "f"(0.f), "f"(0.f), "f"(0.f));
}

struct PrefetchCtx {
    const float* zg;
    const float* wq;
    const float* wk;
    u32 zsu0, zsu1, wsu0, wsu1;
    int tid, b, s0, cbase;
};

__device__ __forceinline__ void prefetch_d(const PrefetchCtx& P, int dd) {
    const int c   = P.cbase + dd;
    const u32 zsu = (dd & 1) ? P.zsu1 : P.zsu0;
    const u32 wsu = (dd & 1) ? P.wsu1 : P.wsu0;
    #pragma unroll
    for (int i = 0; i < 12; i++) {
        int idx  = P.tid + i * NTHREADS;
        int zrow = idx / 48;
        int gq   = idx - zrow * 48;
        const float* src = P.zg + ((size_t)((P.b * RR + zrow) * CC + c)) * ZLEN
                         + KW + P.s0 + gq * 4;
        cpasync16(zsu + (u32)(zrow * ZSTRIDE + gq * 4) * 4u, src);
    }
    cpasync4(wsu + (64 + P.tid) * 4,       P.wk + c * KW + P.tid);
    cpasync4(wsu + (256 + 64 + P.tid) * 4, P.wq + c * KW + P.tid);
    cp_commit();
}

__global__ __launch_bounds__(NTHREADS, 3)
void convspe_mma_kernel(const float* __restrict__ qg,
                        const float* __restrict__ kg,
                        const float* __restrict__ wq,
                        const float* __restrict__ wk,
                        const float* __restrict__ zg,
                        float* __restrict__ out)
{
    extern __shared__ char dyn[];
    u32*   Zs0 = reinterpret_cast<u32*>(dyn);
    u32*   Zs1 = reinterpret_cast<u32*>(dyn + Z_BYTES);
    float* QK  = reinterpret_cast<float*>(dyn + 2 * Z_BYTES);
    float* W0  = reinterpret_cast<float*>(dyn + 2 * Z_BYTES + QK_BYTES);
    float* W1  = reinterpret_cast<float*>(dyn + 2 * Z_BYTES + QK_BYTES + W_BYTES);

    const int tid  = threadIdx.x;
    const int w    = tid >> 5;
    const int lane = tid & 31;
    const int g    = lane >> 2;       // row group 0..7
    const int qi   = lane & 3;        // quad index 0..3

    const int stile = blockIdx.x;     // 0..15
    const int h     = blockIdx.y;     // 0..7
    const int bz    = blockIdx.z;     // 0..15
    const int b     = bz >> 3;
    const int dh    = bz & 7;         // d-split index
    const int dbase = dh * DLOC;
    const int s0    = stile * TS;
    const int cbase = h * DD + dbase;

    // ---- zero-fill both W pads once (out-of-band entries stay 0 forever) ----
    #pragma unroll
    for (int i = 0; i < 4; i++) {
        W0[tid + i * NTHREADS] = 0.f;
        W1[tid + i * NTHREADS] = 0.f;
    }

    // ---- stage q/k transposed for this CTA's 8 d's: QK[dl][row] ----
    for (int idx = tid; idx < TS * 2; idx += NTHREADS) {  // 1 iter
        int srow = idx >> 1;
        int c4   = idx & 1;           // 0..1 (4 floats each -> dl 0..7)
        int goff = (((b * SS + s0 + srow) * HH + h) * DD) + dbase + c4 * 4;
        float4 q4 = *reinterpret_cast<const float4*>(qg + goff);
        float4 k4 = *reinterpret_cast<const float4*>(kg + goff);
        float qa[4] = {q4.x, q4.y, q4.z, q4.w};
        float ka[4] = {k4.x, k4.y, k4.z, k4.w};
        #pragma unroll
        for (int j = 0; j < 4; j++) {
            QK[(c4 * 4 + j) * QKSTRIDE + srow]      = qa[j];
            QK[(c4 * 4 + j) * QKSTRIDE + 64 + srow] = ka[j];
        }
    }

    PrefetchCtx P { zg, wq, wk,
                    smem_u32(Zs0), smem_u32(Zs1), smem_u32(W0), smem_u32(W1),
                    tid, b, s0, cbase };

    // ---- prefetch d = 0 ----
    prefetch_d(P, 0);

    // ---- per-warp constants: warp owns 2 m-tiles of one filter half ----
    const int f      = w >> 1;          // 0: qhat rows (filter wk), 1: khat rows (filter wq)
    const int c0     = (w & 1) * 4;     // chunk base
    const int fbase  = f * 64 + (w & 1) * 32;
    const int qg_off = qi - g;          // lane band offset

    float acc0[4][4], acc1[4][4];       // running d-sums for m-tile0 / m-tile1
    #pragma unroll
    for (int n = 0; n < 4; n++)
        #pragma unroll
        for (int i = 0; i < 4; i++) { acc0[n][i] = 0.f; acc1[n][i] = 0.f; }

    for (int d = 0; d < DLOC; d++) {
        cp_wait_all();        // this thread's cp.async group for d complete
        __syncthreads();      // data for d visible; iteration d-1 consumers done
                              // (this barrier also protects the refill below)

        if (d + 1 < DLOC) prefetch_d(P, d + 1);   // overlaps the MMA loop below

        const u32*   Zs = (d & 1) ? Zs1 : Zs0;
        const float* wp = ((d & 1) ? W1 : W0) + f * 256;

        // -- build unscaled A frags (shared by both m-tiles, verified mapping) --
        u32 aw0[21], aw2[21];
        #pragma unroll
        for (int i = 0; i < 21; i++) {
            aw0[i] = cvt_tf32(wp[40 + 8 * i + qg_off]);
            aw2[i] = cvt_tf32(wp[44 + 8 * i + qg_off]);
        }

        // -- per-d conv via MMA: work = W_band x Z (no q scaling) --
        float work0[4][4], work1[4][4];

        #pragma unroll
        for (int u = 0; u < 20; u++) {
            const int kg = (c0 + u) * 8 + qi;
            u32 b0[4], b1[4];
            #pragma unroll
            for (int n = 0; n < 4; n++) {
                const u32* zr = Zs + (n * 8 + g) * ZSTRIDE + kg;
                b0[n] = zr[0];
                b1[n] = zr[4];
            }

            if (u < 18) {   // m-tile 0: local chunk u
                const u32 a0 = aw0[u + 3], a1 = aw0[u + 2];
                const u32 a2 = aw2[u + 3], a3 = aw2[u + 2];
                if (u == 0) {
                    #pragma unroll
                    for (int n = 0; n < 4; n++)
                        mma_init(work0[n], a0, a1, a2, a3, b0[n], b1[n]);
                } else {
                    #pragma unroll
                    for (int n = 0; n < 4; n++)
                        mma_acc(work0[n], a0, a1, a2, a3, b0[n], b1[n]);
                }
            }
            if (u >= 2) {   // m-tile 1: frags shifted by 2 chunks
                const u32 a0 = aw0[u + 1], a1 = aw0[u];
                const u32 a2 = aw2[u + 1], a3 = aw2[u];
                if (u == 2) {
                    #pragma unroll
                    for (int n = 0; n < 4; n++)
                        mma_init(work1[n], a0, a1, a2, a3, b0[n], b1[n]);
                } else {
                    #pragma unroll
                    for (int n = 0; n < 4; n++)
                        mma_acc(work1[n], a0, a1, a2, a3, b0[n], b1[n]);
                }
            }
        }

        // -- scale by q/k at (s, d) and accumulate over d (exact fp32) --
        const float* qkrow = QK + d * QKSTRIDE + fbase;
        const float qv00 = qkrow[g];
        const float qv01 = qkrow[g + 8];
        const float qv10 = qkrow[g + 16];
        const float qv11 = qkrow[g + 24];
        #pragma unroll
        for (int n = 0; n < 4; n++) {
            acc0[n][0] = fmaf(qv00, work0[n][0], acc0[n][0]);
            acc0[n][1] = fmaf(qv00, work0[n][1], acc0[n][1]);
            acc0[n][2] = fmaf(qv01, work0[n][2], acc0[n][2]);
            acc0[n][3] = fmaf(qv01, work0[n][3], acc0[n][3]);
            acc1[n][0] = fmaf(qv10, work1[n][0], acc1[n][0]);
            acc1[n][1] = fmaf(qv10, work1[n][1], acc1[n][1]);
            acc1[n][2] = fmaf(qv11, work1[n][2], acc1[n][2]);
            acc1[n][3] = fmaf(qv11, work1[n][3], acc1[n][3]);
        }
        // no trailing __syncthreads: the top-of-loop barrier at d+1 orders
        // this iteration's smem reads against the buffer refill at d+2
    }

    // ---- epilogue: dh==0 writes out directly, others write partial scratch ----
    float* obase0 = (dh == 0) ? out : g_part[dh - 1];
    const int khat_off = BB * SS * HH * RR;
    #pragma unroll
    for (int mt = 0; mt < 2; mt++) {
        const int srow = (w & 1) * 32 + mt * 16 + g;
        float* ob  = obase0 + (f ? khat_off : 0)
                   + ((b * SS + s0 + srow) * HH + h) * RR;
        float* ob8 = ob + 8 * HH * RR;     // srow + 8
        #pragma unroll
        for (int n = 0; n < 4; n++) {
            const int col = n * 8 + 2 * qi;
            const float (*acc)[4] = mt ? acc1 : acc0;
            *reinterpret_cast<float2*>(ob  + col) = make_float2(acc[n][0], acc[n][1]);
            *reinterpret_cast<float2*>(ob8 + col) = make_float2(acc[n][2], acc[n][3]);
        }
    }
}

// deterministic combine: out += sum of 7 partials
__global__ __launch_bounds__(256)
void convspe_combine_kernel(float* __restrict__ out)
{
    int i = blockIdx.x * blockDim.x + threadIdx.x;   // float4 index
    if (i >= OUTN / 4) return;
    float4 o = reinterpret_cast<float4*>(out)[i];
    #pragma unroll
    for (int p = 0; p < DSPLIT - 1; p++) {
        float4 v = reinterpret_cast<const float4*>(g_part[p])[i];
        o.x += v.x; o.y += v.y; o.z += v.z; o.w += v.w;
    }
    reinterpret_cast<float4*>(out)[i] = o;
}

extern "C" void kernel_launch(void* const* d_in, const int* in_sizes, int n_in,
                              void* d_out, int out_size)
{
    const float* queries = (const float*)d_in[0];
    const float* keys    = (const float*)d_in[1];
    const float* wq      = (const float*)d_in[2];
    const float* wk      = (const float*)d_in[3];
    const float* z       = (const float*)d_in[4];
    float* out = (float*)d_out;

    cudaFuncSetAttribute(convspe_mma_kernel,
                         cudaFuncAttributeMaxDynamicSharedMemorySize, DYN_BYTES);

    dim3 grid(SS / TS, HH, BB * DSPLIT);   // 16 x 8 x 16 = 2048 CTAs
    dim3 block(NTHREADS);
    convspe_mma_kernel<<<grid, block, DYN_BYTES>>>(queries, keys, wq, wk, z, out);

    int n4 = OUTN / 4;
    convspe_combine_kernel<<<(n4 + 255) / 256, 256>>>(out);
}